// round 2
// baseline (speedup 1.0000x reference)
#include <cuda_runtime.h>

// ---------------------------------------------------------------------------
// ShiftedWindowAttention (Swin block) — round 0 baseline, fp32 SIMT.
//   x:[32,4096,256] -> roll(-4,-4) -> 8x8 windows of 64 tokens
//   qkv = x @ Wqkv^T + b ; per-(window,head) 64x64 attention with rel-pos
//   bias + shift-region mask ; out = attn@v ; proj ; inverse window/roll.
// Shift/window reshuffles are pure index maps fused into GEMM gather/scatter.
// ---------------------------------------------------------------------------

#define NWIN   2048      // 32 batches * 64 windows
#define NTOK   131072    // NWIN * 64 tokens
#define HEADS  8
#define HD     32
#define WS2    64
#define DIM    256
#define ATT_SCALE 0.17677669529663687f   // 32^-0.5

// Scratch (static device arrays: no allocation inside kernel_launch)
__device__ float g_q[NWIN * HEADS * WS2 * HD];
__device__ float g_k[NWIN * HEADS * WS2 * HD];
__device__ float g_v[NWIN * HEADS * WS2 * HD];
__device__ float g_att[NTOK * DIM];

// Token row R (= window*64 + t) -> element offset of that token's row in the
// original x layout, accounting for the roll(-4,-4) + window split. The same
// map is the scatter target for the output (roll(+4,+4) inverse).
__device__ __forceinline__ int src_offset(int R)
{
    int w    = R >> 6;
    int t    = R & 63;
    int b    = w >> 6;
    int widx = w & 63;
    int wy = widx >> 3, wx = widx & 7;
    int ty = t >> 3,    tx = t & 7;
    int ys = ((wy << 3) + ty + 4) & 63;
    int xs = ((wx << 3) + tx + 4) & 63;
    return ((b << 12) + (ys << 6) + xs) * DIM;
}

// ---------------------------------------------------------------------------
// GEMM tiles: 128x64, BK=16, 256 threads, 8x4 register micro-tile.
// ---------------------------------------------------------------------------
#define BM 128
#define BN 64
#define BK 16

__global__ __launch_bounds__(256) void qkv_gemm(
    const float* __restrict__ x,
    const float* __restrict__ w_qkv,
    const float* __restrict__ b_qkv)
{
    __shared__ float As[BK][BM + 4];
    __shared__ float Bs[BK][BN + 4];
    __shared__ int   rowOff[BM];

    const int tid = threadIdx.x;
    const int bx  = blockIdx.x;   // 1024 M tiles
    const int by  = blockIdx.y;   // 12 N tiles (768/64)

    if (tid < BM) rowOff[tid] = src_offset(bx * BM + tid);
    __syncthreads();

    const int tyc = tid >> 4;     // 0..15 -> rows tyc*8..+7
    const int txc = tid & 15;     // 0..15 -> cols txc*4..+3

    float acc[8][4];
#pragma unroll
    for (int i = 0; i < 8; i++)
#pragma unroll
        for (int j = 0; j < 4; j++) acc[i][j] = 0.f;

    for (int k0 = 0; k0 < DIM; k0 += BK) {
        // A: 128 rows x 16 k (gathered rows), 512 float4, 2 per thread
#pragma unroll
        for (int l = 0; l < 2; l++) {
            int idx = tid + l * 256;
            int r   = idx >> 2;
            int c   = (idx & 3) << 2;
            float4 v = *(const float4*)(x + rowOff[r] + k0 + c);
            As[c + 0][r] = v.x; As[c + 1][r] = v.y;
            As[c + 2][r] = v.z; As[c + 3][r] = v.w;
        }
        // B: 64 j-rows x 16 k, 256 float4, 1 per thread
        {
            int j = tid >> 2;
            int c = (tid & 3) << 2;
            float4 v = *(const float4*)(w_qkv + (by * BN + j) * DIM + k0 + c);
            Bs[c + 0][j] = v.x; Bs[c + 1][j] = v.y;
            Bs[c + 2][j] = v.z; Bs[c + 3][j] = v.w;
        }
        __syncthreads();

#pragma unroll
        for (int k = 0; k < BK; k++) {
            float4 a0 = *(const float4*)&As[k][tyc * 8];
            float4 a1 = *(const float4*)&As[k][tyc * 8 + 4];
            float4 b0 = *(const float4*)&Bs[k][txc * 4];
            float a[8] = {a0.x, a0.y, a0.z, a0.w, a1.x, a1.y, a1.z, a1.w};
            float bb[4] = {b0.x, b0.y, b0.z, b0.w};
#pragma unroll
            for (int i = 0; i < 8; i++)
#pragma unroll
                for (int j = 0; j < 4; j++)
                    acc[i][j] = fmaf(a[i], bb[j], acc[i][j]);
        }
        __syncthreads();
    }

    // Epilogue: scatter into q/k/v [win][head][t][d] layout, add bias.
    const int buf = by >> 2;                  // 0:q 1:k 2:v (tile never straddles)
    float* dst = (buf == 0) ? g_q : (buf == 1) ? g_k : g_v;
#pragma unroll
    for (int i = 0; i < 8; i++) {
        int R = bx * BM + tyc * 8 + i;
        int w = R >> 6, t = R & 63;
#pragma unroll
        for (int j = 0; j < 4; j++) {
            int jg  = by * BN + txc * 4 + j;
            int rem = jg & 255;
            int h   = rem >> 5, d = rem & 31;
            dst[(((w << 3) + h) * WS2 + t) * HD + d] = acc[i][j] + __ldg(&b_qkv[jg]);
        }
    }
}

// ---------------------------------------------------------------------------
// Attention: one block per (window, head), 64 threads (1 thread = 1 q row).
// ---------------------------------------------------------------------------
__global__ __launch_bounds__(64) void attn_kernel(const float* __restrict__ pos_enc)
{
    const int w   = blockIdx.x;
    const int h   = blockIdx.y;
    const int tid = threadIdx.x;

    __shared__ float ks[WS2][HD];
    __shared__ float vs[WS2][HD];
    __shared__ float ps[225];
    __shared__ int   rg[WS2];

    const float* kbase = g_k + (w * HEADS + h) * WS2 * HD;
    const float* vbase = g_v + (w * HEADS + h) * WS2 * HD;
    for (int i = tid; i < WS2 * HD; i += 64) {
        (&ks[0][0])[i] = kbase[i];
        (&vs[0][0])[i] = vbase[i];
    }
    for (int i = tid; i < 225; i += 64) ps[i] = pos_enc[h * 225 + i];
    {   // shift-region id for this window's tokens (rolled-frame coords)
        int widx = w & 63;
        int wy = widx >> 3, wx = widx & 7;
        int ry = (wy < 7) ? 0 : ((tid >> 3) < 4 ? 1 : 2);
        int rx = (wx < 7) ? 0 : ((tid & 7) < 4 ? 1 : 2);
        rg[tid] = ry * 3 + rx;
    }
    __syncthreads();

    // own q row -> registers (base is 128B aligned)
    float q[HD];
    const float4* q4 = (const float4*)(g_q + ((w * HEADS + h) * WS2 + tid) * HD);
#pragma unroll
    for (int i = 0; i < 8; i++) {
        float4 v = q4[i];
        q[4 * i + 0] = v.x; q[4 * i + 1] = v.y;
        q[4 * i + 2] = v.z; q[4 * i + 3] = v.w;
    }

    const int y1 = tid >> 3, x1 = tid & 7;
    const int myreg = rg[tid];

    float S[WS2];
#pragma unroll
    for (int tk = 0; tk < WS2; tk++) {
        const float4* kr = (const float4*)ks[tk];
        float dot = 0.f;
#pragma unroll
        for (int d4 = 0; d4 < 8; d4++) {
            float4 kv = kr[d4];
            dot = fmaf(q[4 * d4 + 0], kv.x, dot);
            dot = fmaf(q[4 * d4 + 1], kv.y, dot);
            dot = fmaf(q[4 * d4 + 2], kv.z, dot);
            dot = fmaf(q[4 * d4 + 3], kv.w, dot);
        }
        int y2 = tk >> 3, x2 = tk & 7;
        float s = fmaf(dot, ATT_SCALE, ps[(y1 - y2 + 7) * 15 + (x1 - x2 + 7)]);
        if (rg[tk] != myreg) s = -1e30f;
        S[tk] = s;
    }

    float m = -1e30f;
#pragma unroll
    for (int tk = 0; tk < WS2; tk++) m = fmaxf(m, S[tk]);
    float sum = 0.f;
#pragma unroll
    for (int tk = 0; tk < WS2; tk++) {
        float e = __expf(S[tk] - m);
        S[tk] = e;
        sum  += e;
    }
    const float inv = 1.0f / sum;

    float acc[HD];
#pragma unroll
    for (int d = 0; d < HD; d++) acc[d] = 0.f;
#pragma unroll
    for (int tk = 0; tk < WS2; tk++) {
        float p = S[tk] * inv;
        const float4* vr = (const float4*)vs[tk];
#pragma unroll
        for (int d4 = 0; d4 < 8; d4++) {
            float4 vv = vr[d4];
            acc[4 * d4 + 0] = fmaf(p, vv.x, acc[4 * d4 + 0]);
            acc[4 * d4 + 1] = fmaf(p, vv.y, acc[4 * d4 + 1]);
            acc[4 * d4 + 2] = fmaf(p, vv.z, acc[4 * d4 + 2]);
            acc[4 * d4 + 3] = fmaf(p, vv.w, acc[4 * d4 + 3]);
        }
    }

    float* o = g_att + (w * WS2 + tid) * DIM + h * HD;   // [token][c] layout
#pragma unroll
    for (int i = 0; i < 8; i++)
        ((float4*)o)[i] = make_float4(acc[4 * i + 0], acc[4 * i + 1],
                                      acc[4 * i + 2], acc[4 * i + 3]);
}

// ---------------------------------------------------------------------------
// Output projection: g_att @ w_out^T + b_out, scattered to final positions.
// ---------------------------------------------------------------------------
__global__ __launch_bounds__(256) void out_gemm(
    const float* __restrict__ w_out,
    const float* __restrict__ b_out,
    float* __restrict__ out)
{
    __shared__ float As[BK][BM + 4];
    __shared__ float Bs[BK][BN + 4];
    __shared__ int   dstOff[BM];

    const int tid = threadIdx.x;
    const int bx  = blockIdx.x;   // 1024 M tiles
    const int by  = blockIdx.y;   // 4 N tiles (256/64)

    if (tid < BM) dstOff[tid] = src_offset(bx * BM + tid);
    __syncthreads();

    const int tyc = tid >> 4;
    const int txc = tid & 15;

    float acc[8][4];
#pragma unroll
    for (int i = 0; i < 8; i++)
#pragma unroll
        for (int j = 0; j < 4; j++) acc[i][j] = 0.f;

    const float* abase = g_att + (size_t)bx * BM * DIM;

    for (int k0 = 0; k0 < DIM; k0 += BK) {
#pragma unroll
        for (int l = 0; l < 2; l++) {
            int idx = tid + l * 256;
            int r   = idx >> 2;
            int c   = (idx & 3) << 2;
            float4 v = *(const float4*)(abase + r * DIM + k0 + c);
            As[c + 0][r] = v.x; As[c + 1][r] = v.y;
            As[c + 2][r] = v.z; As[c + 3][r] = v.w;
        }
        {
            int j = tid >> 2;
            int c = (tid & 3) << 2;
            float4 v = *(const float4*)(w_out + (by * BN + j) * DIM + k0 + c);
            Bs[c + 0][j] = v.x; Bs[c + 1][j] = v.y;
            Bs[c + 2][j] = v.z; Bs[c + 3][j] = v.w;
        }
        __syncthreads();

#pragma unroll
        for (int k = 0; k < BK; k++) {
            float4 a0 = *(const float4*)&As[k][tyc * 8];
            float4 a1 = *(const float4*)&As[k][tyc * 8 + 4];
            float4 b0 = *(const float4*)&Bs[k][txc * 4];
            float a[8] = {a0.x, a0.y, a0.z, a0.w, a1.x, a1.y, a1.z, a1.w};
            float bb[4] = {b0.x, b0.y, b0.z, b0.w};
#pragma unroll
            for (int i = 0; i < 8; i++)
#pragma unroll
                for (int j = 0; j < 4; j++)
                    acc[i][j] = fmaf(a[i], bb[j], acc[i][j]);
        }
        __syncthreads();
    }

#pragma unroll
    for (int i = 0; i < 8; i++) {
        int rloc = tyc * 8 + i;
        int off  = dstOff[rloc];
#pragma unroll
        for (int j = 0; j < 4; j++) {
            int jg = by * BN + txc * 4 + j;
            out[off + jg] = acc[i][j] + __ldg(&b_out[jg]);
        }
    }
}

// ---------------------------------------------------------------------------
extern "C" void kernel_launch(void* const* d_in, const int* in_sizes, int n_in,
                              void* d_out, int out_size)
{
    const float* x       = (const float*)d_in[0];
    const float* w_qkv   = (const float*)d_in[1];
    const float* b_qkv   = (const float*)d_in[2];
    const float* w_out   = (const float*)d_in[3];
    const float* b_out   = (const float*)d_in[4];
    const float* pos_enc = (const float*)d_in[5];
    float* out = (float*)d_out;

    qkv_gemm<<<dim3(NTOK / BM, 768 / BN), 256>>>(x, w_qkv, b_qkv);
    attn_kernel<<<dim3(NWIN, HEADS), 64>>>(pos_enc);
    out_gemm<<<dim3(NTOK / BM, DIM / BN), 256>>>(w_out, b_out, out);
}

// round 4
// speedup vs baseline: 1.6006x; 1.6006x over previous
#include <cuda_runtime.h>
#include <cuda_bf16.h>
#include <cstdint>

// ---------------------------------------------------------------------------
// ShiftedWindowAttention — round 3: mma.sync (HMMA) bf16 split-precision GEMMs.
// tcgen05 is unavailable (harness compiles via compute_103 virtual arch, which
// rejects all 'a'-suffix accelerated features). mma.sync.m16n8k16 bf16 is
// baseline PTX and still uses the tensor pipe.
//   C = A@B^T with A,B split into bf16 hi+lo; 3 products (HH, HL, LH) -> ~1e-5.
// ---------------------------------------------------------------------------

#define NWIN   2048
#define NTOK   131072
#define HEADS  8
#define HD     32
#define WS2    64
#define DIM    256
#define ATT_SCALE 0.17677669529663687f

// ---------------- scratch (static device arrays; no allocation) ------------
__device__ __nv_bfloat16 g_xh[NTOK * DIM];
__device__ __nv_bfloat16 g_xl[NTOK * DIM];
__device__ __nv_bfloat16 g_wqh[768 * DIM];
__device__ __nv_bfloat16 g_wql[768 * DIM];
__device__ __nv_bfloat16 g_woh[DIM * DIM];
__device__ __nv_bfloat16 g_wol[DIM * DIM];
__device__ float g_q[NWIN * HEADS * WS2 * HD];
__device__ float g_k[NWIN * HEADS * WS2 * HD];
__device__ float g_v[NWIN * HEADS * WS2 * HD];
__device__ __nv_bfloat16 g_ath[NTOK * DIM];
__device__ __nv_bfloat16 g_atl[NTOK * DIM];

// ---------------- helpers ---------------------------------------------------
__device__ __forceinline__ uint32_t smem_u32(const void* p) {
    uint32_t a;
    asm("{ .reg .u64 t; cvta.to.shared.u64 t, %1; cvt.u32.u64 %0, t; }"
        : "=r"(a) : "l"(p));
    return a;
}
__device__ __forceinline__ void ldsm4(uint32_t& r0, uint32_t& r1,
                                      uint32_t& r2, uint32_t& r3, uint32_t a) {
    asm volatile("ldmatrix.sync.aligned.m8n8.x4.shared.b16 {%0,%1,%2,%3}, [%4];"
                 : "=r"(r0), "=r"(r1), "=r"(r2), "=r"(r3) : "r"(a));
}
#define MMA16816(c, a, b)                                                  \
    asm volatile("mma.sync.aligned.m16n8k16.row.col.f32.bf16.bf16.f32 "    \
        "{%0,%1,%2,%3}, {%4,%5,%6,%7}, {%8,%9}, {%0,%1,%2,%3};"            \
        : "+f"((c)[0]), "+f"((c)[1]), "+f"((c)[2]), "+f"((c)[3])           \
        : "r"((a)[0]), "r"((a)[1]), "r"((a)[2]), "r"((a)[3]),              \
          "r"((b)[0]), "r"((b)[1]))

// ---------------- index map (roll -4,-4 + window split) --------------------
__device__ __forceinline__ int src_offset(int R) {
    int w = R >> 6, t = R & 63;
    int b = w >> 6, widx = w & 63;
    int wy = widx >> 3, wx = widx & 7;
    int ty = t >> 3, tx = t & 7;
    int ys = ((wy << 3) + ty + 4) & 63;
    int xs = ((wx << 3) + tx + 4) & 63;
    return ((b << 12) + (ys << 6) + xs) * DIM;
}

// ---------------- fp32 -> bf16 hi/lo split ---------------------------------
__global__ __launch_bounds__(256) void conv_split(
    const float* __restrict__ src, __nv_bfloat16* __restrict__ hp,
    __nv_bfloat16* __restrict__ lp, int n4)
{
    int i = blockIdx.x * 256 + threadIdx.x;
    if (i >= n4) return;
    float4 v = ((const float4*)src)[i];
    __nv_bfloat16 h0 = __float2bfloat16_rn(v.x);
    __nv_bfloat16 h1 = __float2bfloat16_rn(v.y);
    __nv_bfloat16 h2 = __float2bfloat16_rn(v.z);
    __nv_bfloat16 h3 = __float2bfloat16_rn(v.w);
    __nv_bfloat16 l0 = __float2bfloat16_rn(v.x - __bfloat162float(h0));
    __nv_bfloat16 l1 = __float2bfloat16_rn(v.y - __bfloat162float(h1));
    __nv_bfloat16 l2 = __float2bfloat16_rn(v.z - __bfloat162float(h2));
    __nv_bfloat16 l3 = __float2bfloat16_rn(v.w - __bfloat162float(h3));
    ((__nv_bfloat162*)hp)[2 * i + 0] = __halves2bfloat162(h0, h1);
    ((__nv_bfloat162*)hp)[2 * i + 1] = __halves2bfloat162(h2, h3);
    ((__nv_bfloat162*)lp)[2 * i + 0] = __halves2bfloat162(l0, l1);
    ((__nv_bfloat162*)lp)[2 * i + 1] = __halves2bfloat162(l2, l3);
}

// ---------------------------------------------------------------------------
// HMMA GEMM: C[M=131072, Ntot] = A[M,256] @ B[Ntot,256]^T (split bf16).
// MODE 0: qkv (A rows gathered; scatter to g_q/g_k/g_v + bias)
// MODE 1: out-proj (A linear; scatter via src_offset + bias)
// CTA: 128-row M-tile, full-K A (hi+lo) in SMEM, loops N-tiles of 128,
// B chunks [128][32] double-buffered with register prefetch.
// 8 warps: warp_m=wid&3 (32 rows), warp_n=wid>>2 (64 cols).
// SMEM bf16 row strides: A 264 (pad 8), B 40 (pad 8) -> conflict-free ldmatrix.
// ---------------------------------------------------------------------------
#define A_STR   264
#define B_STR   40
#define A_OFF   1024
#define A_SPL   67584              // 128*264*2
#define B_OFF   (A_OFF + 2 * A_SPL)       // 136192
#define B_SPL   10240              // 128*40*2
#define B_BUF   (2 * B_SPL)        // hi+lo per buffer
#define SMEM_SZ (B_OFF + 2 * B_BUF)       // 177152

template <int MODE>
__global__ __launch_bounds__(256) void gemm_tc(
    const __nv_bfloat16* __restrict__ Ah, const __nv_bfloat16* __restrict__ Al,
    const __nv_bfloat16* __restrict__ Bh, const __nv_bfloat16* __restrict__ Bl,
    const float* __restrict__ bias, float* __restrict__ outp)
{
    constexpr int NTILES = (MODE == 0) ? 6 : 2;
    extern __shared__ char smem[];
    const uint32_t sbase = smem_u32(smem);
    const int tid  = threadIdx.x;
    const int wid  = tid >> 5;
    const int lane = tid & 31;
    const int bx   = blockIdx.x;
    const int warp_m = wid & 3;
    const int warp_n = wid >> 2;
    const int m0 = warp_m * 32;
    const int n0 = warp_n * 64;

    int* rowOff = (int*)smem;
    if (tid < 128) {
        int R = bx * 128 + tid;
        rowOff[tid] = (MODE == 0) ? src_offset(R) : R * DIM;
    }
    __syncthreads();

    // ---- load full-K A tile (hi+lo) into SMEM (stride A_STR) ----
#pragma unroll
    for (int i = 0; i < 32; i++) {
        int idx = tid + i * 256;           // 8192 uint4
        int u  = idx & 31;                 // 32 uint4 per row
        int r  = (idx >> 5) & 127;
        int hl = idx >> 12;
        const __nv_bfloat16* s = (hl ? Al : Ah) + rowOff[r] + u * 8;
        uint4 v = *(const uint4*)s;
        *(uint4*)(smem + A_OFF + hl * A_SPL + (r * A_STR + u * 8) * 2) = v;
    }

    // ldmatrix lane-address components
    const int a_row = lane & 15;
    const int a_col = (lane >> 4) * 8;
    const int b_row = (lane & 7) + ((lane >> 4) << 3);
    const int b_col = ((lane >> 3) & 1) * 8;
    const uint32_t aAddrH = sbase + A_OFF +
        ((m0 + a_row) * A_STR + a_col) * 2;
    const uint32_t aAddrL = aAddrH + A_SPL;

#pragma unroll 1
    for (int nt = 0; nt < NTILES; nt++) {
        const int nb = nt * 128;           // global B row base

        // load B chunk 0 -> buffer 0
        __syncthreads();
#pragma unroll
        for (int i = 0; i < 4; i++) {
            int idx = tid + i * 256;       // 1024 uint4
            int hl = idx >> 9, r = (idx >> 2) & 127, u = idx & 3;
            const __nv_bfloat16* s = (hl ? Bl : Bh) + (nb + r) * DIM + u * 8;
            uint4 v = *(const uint4*)s;
            *(uint4*)(smem + B_OFF + hl * B_SPL + (r * B_STR + u * 8) * 2) = v;
        }
        __syncthreads();

        float acc[2][8][4];
#pragma unroll
        for (int mf = 0; mf < 2; mf++)
#pragma unroll
            for (int nf = 0; nf < 8; nf++)
#pragma unroll
                for (int q = 0; q < 4; q++) acc[mf][nf][q] = 0.f;

#pragma unroll 1
        for (int c = 0; c < 8; c++) {
            // prefetch next chunk to registers
            uint4 pre[4];
            if (c < 7) {
#pragma unroll
                for (int i = 0; i < 4; i++) {
                    int idx = tid + i * 256;
                    int hl = idx >> 9, r = (idx >> 2) & 127, u = idx & 3;
                    pre[i] = *(const uint4*)((hl ? Bl : Bh) +
                             (nb + r) * DIM + (c + 1) * 32 + u * 8);
                }
            }

            const uint32_t bBase = sbase + B_OFF + (c & 1) * B_BUF;
#pragma unroll
            for (int ks = 0; ks < 2; ks++) {
                const int kk = c * 32 + ks * 16;
                uint32_t ah[2][4], al[2][4], bh[8][2], bl[8][2];
#pragma unroll
                for (int mf = 0; mf < 2; mf++) {
                    ldsm4(ah[mf][0], ah[mf][1], ah[mf][2], ah[mf][3],
                          aAddrH + (mf * 16 * A_STR + kk) * 2);
                    ldsm4(al[mf][0], al[mf][1], al[mf][2], al[mf][3],
                          aAddrL + (mf * 16 * A_STR + kk) * 2);
                }
#pragma unroll
                for (int nf2 = 0; nf2 < 4; nf2++) {
                    uint32_t ba = bBase +
                        ((n0 + nf2 * 16 + b_row) * B_STR + ks * 16 + b_col) * 2;
                    ldsm4(bh[2 * nf2][0], bh[2 * nf2][1],
                          bh[2 * nf2 + 1][0], bh[2 * nf2 + 1][1], ba);
                    ldsm4(bl[2 * nf2][0], bl[2 * nf2][1],
                          bl[2 * nf2 + 1][0], bl[2 * nf2 + 1][1], ba + B_SPL);
                }
#pragma unroll
                for (int mf = 0; mf < 2; mf++)
#pragma unroll
                    for (int nf = 0; nf < 8; nf++)
                        MMA16816(acc[mf][nf], ah[mf], bh[nf]);
#pragma unroll
                for (int mf = 0; mf < 2; mf++)
#pragma unroll
                    for (int nf = 0; nf < 8; nf++)
                        MMA16816(acc[mf][nf], ah[mf], bl[nf]);
#pragma unroll
                for (int mf = 0; mf < 2; mf++)
#pragma unroll
                    for (int nf = 0; nf < 8; nf++)
                        MMA16816(acc[mf][nf], al[mf], bh[nf]);
            }
            __syncthreads();
            if (c < 7) {
#pragma unroll
                for (int i = 0; i < 4; i++) {
                    int idx = tid + i * 256;
                    int hl = idx >> 9, r = (idx >> 2) & 127, u = idx & 3;
                    *(uint4*)(smem + B_OFF + ((c + 1) & 1) * B_BUF +
                              hl * B_SPL + (r * B_STR + u * 8) * 2) = pre[i];
                }
            }
            __syncthreads();
        }

        // ---- epilogue: bias + scatter ----
        // C frag: c0,c1 -> row t/4,      cols (t%4)*2, +1
        //         c2,c3 -> row t/4 + 8,  same cols
        const int erow = lane >> 2;
        const int ecol = (lane & 3) * 2;
#pragma unroll
        for (int mf = 0; mf < 2; mf++) {
            int R0 = bx * 128 + m0 + mf * 16 + erow;
#pragma unroll
            for (int nf = 0; nf < 8; nf++) {
                int jg = nt * 128 + n0 + nf * 8 + ecol;
                float bx0 = __ldg(&bias[jg]);
                float bx1 = __ldg(&bias[jg + 1]);
                float2 v0 = make_float2(acc[mf][nf][0] + bx0,
                                        acc[mf][nf][1] + bx1);
                float2 v1 = make_float2(acc[mf][nf][2] + bx0,
                                        acc[mf][nf][3] + bx1);
                if (MODE == 0) {
                    int buf = jg >> 8;
                    float* dst = (buf == 0) ? g_q : (buf == 1) ? g_k : g_v;
                    int rem = jg & 255;
                    int h = rem >> 5, d = rem & 31;
                    int w0 = R0 >> 6, t0 = R0 & 63;
                    *(float2*)&dst[(((w0 << 3) + h) * WS2 + t0) * HD + d] = v0;
                    int R1 = R0 + 8;
                    int w1 = R1 >> 6, t1 = R1 & 63;
                    *(float2*)&dst[(((w1 << 3) + h) * WS2 + t1) * HD + d] = v1;
                } else {
                    *(float2*)&outp[src_offset(R0) + jg] = v0;
                    *(float2*)&outp[src_offset(R0 + 8) + jg] = v1;
                }
            }
        }
    }
}

// ---------------------------------------------------------------------------
// Attention: 128 threads = 2 heads of one window; fp32; writes bf16 hi/lo.
// ---------------------------------------------------------------------------
__global__ __launch_bounds__(128) void attn_kernel(const float* __restrict__ pos_enc)
{
    const int w = blockIdx.x;
    const int tid = threadIdx.x;
    const int hh = tid >> 6;
    const int t = tid & 63;
    const int h = blockIdx.y * 2 + hh;

    __shared__ float ks[2][WS2][HD];
    __shared__ float vs[2][WS2][HD];
    __shared__ float ps[2][225];
    __shared__ int   rg[WS2];

    const float* kbase = g_k + (w * HEADS + h) * WS2 * HD;
    const float* vbase = g_v + (w * HEADS + h) * WS2 * HD;
    for (int i = t; i < WS2 * HD; i += 64) {
        (&ks[hh][0][0])[i] = kbase[i];
        (&vs[hh][0][0])[i] = vbase[i];
    }
    for (int i = t; i < 225; i += 64) ps[hh][i] = pos_enc[h * 225 + i];
    if (tid < 64) {
        int widx = w & 63;
        int wy = widx >> 3, wx = widx & 7;
        int ry = (wy < 7) ? 0 : ((tid >> 3) < 4 ? 1 : 2);
        int rx = (wx < 7) ? 0 : ((tid & 7) < 4 ? 1 : 2);
        rg[tid] = ry * 3 + rx;
    }
    __syncthreads();

    float q[HD];
    const float4* q4 = (const float4*)(g_q + ((w * HEADS + h) * WS2 + t) * HD);
#pragma unroll
    for (int i = 0; i < 8; i++) {
        float4 v = q4[i];
        q[4 * i + 0] = v.x; q[4 * i + 1] = v.y;
        q[4 * i + 2] = v.z; q[4 * i + 3] = v.w;
    }

    const int y1 = t >> 3, x1 = t & 7;
    const int myreg = rg[t];

    float S[WS2];
#pragma unroll
    for (int tk = 0; tk < WS2; tk++) {
        const float4* kr = (const float4*)ks[hh][tk];
        float dot = 0.f;
#pragma unroll
        for (int d4 = 0; d4 < 8; d4++) {
            float4 kv = kr[d4];
            dot = fmaf(q[4 * d4 + 0], kv.x, dot);
            dot = fmaf(q[4 * d4 + 1], kv.y, dot);
            dot = fmaf(q[4 * d4 + 2], kv.z, dot);
            dot = fmaf(q[4 * d4 + 3], kv.w, dot);
        }
        int y2 = tk >> 3, x2 = tk & 7;
        float s = fmaf(dot, ATT_SCALE, ps[hh][(y1 - y2 + 7) * 15 + (x1 - x2 + 7)]);
        if (rg[tk] != myreg) s = -1e30f;
        S[tk] = s;
    }

    float m = -1e30f;
#pragma unroll
    for (int tk = 0; tk < WS2; tk++) m = fmaxf(m, S[tk]);
    float sum = 0.f;
#pragma unroll
    for (int tk = 0; tk < WS2; tk++) {
        float e = __expf(S[tk] - m);
        S[tk] = e;
        sum += e;
    }
    const float inv = 1.0f / sum;

    float acc[HD];
#pragma unroll
    for (int d = 0; d < HD; d++) acc[d] = 0.f;
#pragma unroll
    for (int tk = 0; tk < WS2; tk++) {
        float p = S[tk] * inv;
        const float4* vr = (const float4*)vs[hh][tk];
#pragma unroll
        for (int d4 = 0; d4 < 8; d4++) {
            float4 vv = vr[d4];
            acc[4 * d4 + 0] = fmaf(p, vv.x, acc[4 * d4 + 0]);
            acc[4 * d4 + 1] = fmaf(p, vv.y, acc[4 * d4 + 1]);
            acc[4 * d4 + 2] = fmaf(p, vv.z, acc[4 * d4 + 2]);
            acc[4 * d4 + 3] = fmaf(p, vv.w, acc[4 * d4 + 3]);
        }
    }

    __nv_bfloat162* oh = (__nv_bfloat162*)(g_ath + (w * WS2 + t) * DIM + h * HD);
    __nv_bfloat162* ol = (__nv_bfloat162*)(g_atl + (w * WS2 + t) * DIM + h * HD);
#pragma unroll
    for (int i = 0; i < 16; i++) {
        float a = acc[2 * i], b = acc[2 * i + 1];
        __nv_bfloat16 ahv = __float2bfloat16_rn(a);
        __nv_bfloat16 bhv = __float2bfloat16_rn(b);
        __nv_bfloat16 alv = __float2bfloat16_rn(a - __bfloat162float(ahv));
        __nv_bfloat16 blv = __float2bfloat16_rn(b - __bfloat162float(bhv));
        oh[i] = __halves2bfloat162(ahv, bhv);
        ol[i] = __halves2bfloat162(alv, blv);
    }
}

// ---------------------------------------------------------------------------
extern "C" void kernel_launch(void* const* d_in, const int* in_sizes, int n_in,
                              void* d_out, int out_size)
{
    const float* x       = (const float*)d_in[0];
    const float* w_qkv   = (const float*)d_in[1];
    const float* b_qkv   = (const float*)d_in[2];
    const float* w_out   = (const float*)d_in[3];
    const float* b_out   = (const float*)d_in[4];
    const float* pos_enc = (const float*)d_in[5];
    float* out = (float*)d_out;

    cudaFuncSetAttribute(gemm_tc<0>, cudaFuncAttributeMaxDynamicSharedMemorySize, SMEM_SZ);
    cudaFuncSetAttribute(gemm_tc<1>, cudaFuncAttributeMaxDynamicSharedMemorySize, SMEM_SZ);

    __nv_bfloat16 *xh, *xl, *wqh, *wql, *woh, *wol, *ath, *atl;
    cudaGetSymbolAddress((void**)&xh,  g_xh);
    cudaGetSymbolAddress((void**)&xl,  g_xl);
    cudaGetSymbolAddress((void**)&wqh, g_wqh);
    cudaGetSymbolAddress((void**)&wql, g_wql);
    cudaGetSymbolAddress((void**)&woh, g_woh);
    cudaGetSymbolAddress((void**)&wol, g_wol);
    cudaGetSymbolAddress((void**)&ath, g_ath);
    cudaGetSymbolAddress((void**)&atl, g_atl);

    conv_split<<<(NTOK * DIM / 4 + 255) / 256, 256>>>(x, xh, xl, NTOK * DIM / 4);
    conv_split<<<(768 * DIM / 4 + 255) / 256, 256>>>(w_qkv, wqh, wql, 768 * DIM / 4);
    conv_split<<<(DIM * DIM / 4 + 255) / 256, 256>>>(w_out, woh, wol, DIM * DIM / 4);

    gemm_tc<0><<<NTOK / 128, 256, SMEM_SZ>>>(xh, xl, wqh, wql, b_qkv, nullptr);
    attn_kernel<<<dim3(NWIN, HEADS / 2), 128>>>(pos_enc);
    gemm_tc<1><<<NTOK / 128, 256, SMEM_SZ>>>(ath, atl, woh, wol, b_out, out);
}